// round 4
// baseline (speedup 1.0000x reference)
#include <cuda_runtime.h>
#include <math.h>
#include <stdint.h>

// Problem constants (fixed by the reference)
#define BB 16
#define HH 32
#define DD 128
#define GG 8
#define SS 8192
#define KVG 4         // HH / GG : queries per kv group
#define NSPLIT 64     // splits per (b,g)
#define SPLIT_LEN 128 // SS / NSPLIT
#define WPB 8         // warps per block in partial kernel
#define NEG_BIG (-1.0e30f)

// Scratch: per (b,g,split,q): acc[D] and (m,l)
__device__ float  g_acc[(size_t)BB * GG * NSPLIT * KVG * DD]; // 16 MB
__device__ float2 g_ml[(size_t)BB * GG * NSPLIT * KVG];

__device__ __forceinline__ float ex2f(float x) {
    float y;
    asm("ex2.approx.ftz.f32 %0, %1;" : "=f"(y) : "f"(x));
    return y;
}

__global__ void __launch_bounds__(256, 2)
attn_partial(const float* __restrict__ Q,
             const float* __restrict__ K,
             const float* __restrict__ V,
             const int*   __restrict__ cache_seqlen)
{
    const int b    = blockIdx.z;
    const int g    = blockIdx.y;
    const int warp = threadIdx.x >> 5;
    const int lane = threadIdx.x & 31;
    const int split = blockIdx.x * WPB + warp;

    const int len  = cache_seqlen[b];
    const int s0   = split * SPLIT_LEN;
    const int n    = min(s0 + SPLIT_LEN, len) - s0;
    if (n <= 0) return;   // combine never reads inactive splits

    // Q for the 4 queries of this group; fold softmax scale * log2(e)
    const float scale = 0.08838834764831845f * 1.4426950408889634f;
    float4 qv[KVG];
#pragma unroll
    for (int q = 0; q < KVG; q++) {
        const float4* qp = (const float4*)(Q + ((size_t)(b * HH + g * KVG + q)) * DD);
        float4 t = qp[lane];
        qv[q] = make_float4(t.x * scale, t.y * scale, t.z * scale, t.w * scale);
    }

    float  m[KVG], l[KVG];
    float4 acc[KVG];
#pragma unroll
    for (int q = 0; q < KVG; q++) {
        m[q] = NEG_BIG;
        l[q] = 0.f;
        acc[q] = make_float4(0.f, 0.f, 0.f, 0.f);
    }

    const int strideF4 = (GG * DD) / 4;   // float4 stride between tokens = 256
    const float4* kp = (const float4*)(K + (((size_t)b * SS + s0) * GG + g) * DD) + lane;
    const float4* vp = (const float4*)(V + (((size_t)b * SS + s0) * GG + g) * DD) + lane;

    // Preload batch 0 (loads inside the split are always within the S=8192 allocation)
    float4 kc[4], vc[4];
#pragma unroll
    for (int t = 0; t < 4; t++) kc[t] = kp[t * strideF4];
#pragma unroll
    for (int t = 0; t < 4; t++) vc[t] = vp[t * strideF4];

    for (int i = 0; i < n; i += 4) {
        const int rem = n - i;   // >= 1

        // 1) Dot products on current K (frees kc registers early)
        float sc[4][KVG];
#pragma unroll
        for (int t = 0; t < 4; t++)
#pragma unroll
            for (int q = 0; q < KVG; q++)
                sc[t][q] = qv[q].x * kc[t].x + qv[q].y * kc[t].y +
                           qv[q].z * kc[t].z + qv[q].w * kc[t].w;

        // 2) Issue next batch's loads NOW (8 LDG.128 in flight through all compute below)
        const int adv = (i + 4 < SPLIT_LEN) ? 4 * strideF4 : 0;  // clamp final prefetch in-bounds
        kp += adv; vp += adv;
        float4 kn[4], vn[4];
#pragma unroll
        for (int t = 0; t < 4; t++) kn[t] = kp[t * strideF4];
#pragma unroll
        for (int t = 0; t < 4; t++) vn[t] = vp[t * strideF4];

        // 3) Butterfly reduce 16 independent values (deep ILP across chains)
#pragma unroll
        for (int off = 16; off; off >>= 1)
#pragma unroll
            for (int t = 0; t < 4; t++)
#pragma unroll
                for (int q = 0; q < KVG; q++)
                    sc[t][q] += __shfl_xor_sync(0xffffffffu, sc[t][q], off);

        // 4) Mask tokens past the valid length (warp-uniform predicated selects)
#pragma unroll
        for (int t = 1; t < 4; t++)
            if (t >= rem)
#pragma unroll
                for (int q = 0; q < KVG; q++)
                    sc[t][q] = NEG_BIG;

        // 5) One rescale per q per batch; no branches; consumes vc
#pragma unroll
        for (int q = 0; q < KVG; q++) {
            float mb = fmaxf(fmaxf(sc[0][q], sc[1][q]), fmaxf(sc[2][q], sc[3][q]));
            float mn = fmaxf(m[q], mb);
            float alpha = ex2f(m[q] - mn);
            m[q] = mn;
            float p0 = ex2f(sc[0][q] - mn);
            float p1 = ex2f(sc[1][q] - mn);
            float p2 = ex2f(sc[2][q] - mn);
            float p3 = ex2f(sc[3][q] - mn);
            l[q] = l[q] * alpha + ((p0 + p1) + (p2 + p3));
            float ax = acc[q].x * alpha, ay = acc[q].y * alpha,
                  az = acc[q].z * alpha, aw = acc[q].w * alpha;
            ax += p0 * vc[0].x; ay += p0 * vc[0].y; az += p0 * vc[0].z; aw += p0 * vc[0].w;
            ax += p1 * vc[1].x; ay += p1 * vc[1].y; az += p1 * vc[1].z; aw += p1 * vc[1].w;
            ax += p2 * vc[2].x; ay += p2 * vc[2].y; az += p2 * vc[2].z; aw += p2 * vc[2].w;
            ax += p3 * vc[3].x; ay += p3 * vc[3].y; az += p3 * vc[3].z; aw += p3 * vc[3].w;
            acc[q] = make_float4(ax, ay, az, aw);
        }

        // 6) Rotate buffers (ptxas renames via unrolled copies)
#pragma unroll
        for (int t = 0; t < 4; t++) { kc[t] = kn[t]; vc[t] = vn[t]; }
    }

    const size_t sg = ((size_t)(b * GG + g)) * NSPLIT + split;
#pragma unroll
    for (int q = 0; q < KVG; q++) {
        float4* ap = (float4*)(g_acc + (sg * KVG + q) * DD) + lane;
        *ap = acc[q];
        if (lane == 0) g_ml[sg * KVG + q] = make_float2(m[q], l[q]);
    }
}

__global__ void __launch_bounds__(128)
attn_combine(const int* __restrict__ cache_seqlen, float* __restrict__ out)
{
    const int h = blockIdx.x;   // 0..HH-1
    const int b = blockIdx.y;   // 0..BB-1
    const int g = h / KVG;
    const int q = h % KVG;
    const int d = threadIdx.x;  // 0..127

    const int len  = cache_seqlen[b];
    const int nact = (len + SPLIT_LEN - 1) / SPLIT_LEN;   // active splits, >= 8

    const size_t base = ((size_t)(b * GG + g)) * NSPLIT * KVG + q;

    __shared__ float2 s_ml[NSPLIT];
    if (threadIdx.x < nact)
        s_ml[threadIdx.x] = g_ml[base + (size_t)threadIdx.x * KVG];
    __syncthreads();

    float M = NEG_BIG;
    for (int i = 0; i < nact; i++) M = fmaxf(M, s_ml[i].x);

    float num = 0.f, den = 0.f;
#pragma unroll 8
    for (int i = 0; i < nact; i++) {
        float2 ml = s_ml[i];
        float w = ex2f(ml.x - M);
        den += w * ml.y;
        num += w * g_acc[(base + (size_t)i * KVG) * DD + d];
    }

    out[((size_t)b * HH + h) * DD + d] = num / den;
}

extern "C" void kernel_launch(void* const* d_in, const int* in_sizes, int n_in,
                              void* d_out, int out_size)
{
    const float* Q  = (const float*)d_in[0];
    const float* K  = (const float*)d_in[1];
    const float* V  = (const float*)d_in[2];
    const int* csl  = (const int*)d_in[3];
    float* out      = (float*)d_out;

    dim3 grid1(NSPLIT / WPB, GG, BB);   // 8 x 8 x 16 = 1024 blocks
    attn_partial<<<grid1, 256>>>(Q, K, V, csl);

    dim3 grid2(HH, BB);                 // 32 x 16 = 512 blocks
    attn_combine<<<grid2, 128>>>(csl, out);
}

// round 5
// speedup vs baseline: 1.1442x; 1.1442x over previous
#include <cuda_runtime.h>
#include <math.h>
#include <stdint.h>

#define BB 16
#define HH 32
#define DD 128
#define GG 8
#define SS 8192
#define KVG 4         // HH / GG
#define NSPLIT 64
#define SPLIT_LEN 128 // SS / NSPLIT
#define WPB 8
#define NEG_BIG (-1.0e30f)

__device__ float  g_acc[(size_t)BB * GG * NSPLIT * KVG * DD]; // 16 MB
__device__ float2 g_ml[(size_t)BB * GG * NSPLIT * KVG];

__device__ __forceinline__ float ex2f(float x) {
    float y;
    asm("ex2.approx.ftz.f32 %0, %1;" : "=f"(y) : "f"(x));
    return y;
}
__device__ __forceinline__ float shflx(float v, int off) {
    return __shfl_xor_sync(0xffffffffu, v, off);
}
__device__ __forceinline__ float shfli(float v, int src) {
    return __shfl_sync(0xffffffffu, v, src);
}

__global__ void noop_pad() {}

__global__ void __launch_bounds__(256, 2)
attn_partial(const float* __restrict__ Q,
             const float* __restrict__ K,
             const float* __restrict__ V,
             const int*   __restrict__ cache_seqlen)
{
    const int b    = blockIdx.z;
    const int g    = blockIdx.y;
    const int lane = threadIdx.x & 31;
    const int split = blockIdx.x * WPB + (threadIdx.x >> 5);

    const int len  = cache_seqlen[b];
    const int s0   = split * SPLIT_LEN;
    const int n    = min(s0 + SPLIT_LEN, len) - s0;   // may be <= 0

    // lane's token index within a 4-batch under the bit-reversed reduce mapping:
    // value v = bitrev4(lane&15), q = v>>2, t = v&3
    const int t_lane = (((lane >> 2) & 1) << 1) | ((lane >> 3) & 1);

    const float scale = 0.08838834764831845f * 1.4426950408889634f; // 1/sqrt(128)*log2e
    float4 qv[KVG];
#pragma unroll
    for (int q = 0; q < KVG; q++) {
        const float4* qp = (const float4*)(Q + ((size_t)(b * HH + g * KVG + q)) * DD);
        float4 t = qp[lane];
        qv[q] = make_float4(t.x * scale, t.y * scale, t.z * scale, t.w * scale);
    }

    float  m[KVG], l[KVG];
    float4 acc[KVG];
#pragma unroll
    for (int q = 0; q < KVG; q++) {
        m[q] = NEG_BIG; l[q] = 0.f;
        acc[q] = make_float4(0.f, 0.f, 0.f, 0.f);
    }
    float mq_lane = NEG_BIG;  // per-lane copy of m for this lane's q

    const int strideF4 = (GG * DD) / 4;   // 256 float4 between tokens
    const float4* kp = (const float4*)(K + (((size_t)b * SS + s0) * GG + g) * DD) + lane;
    const float4* vp = (const float4*)(V + (((size_t)b * SS + s0) * GG + g) * DD) + lane;

    for (int i = 0; i < n; i += 4) {
        const int rem = n - i;   // >= 1

        float4 kb[4], vb[4];
#pragma unroll
        for (int t = 0; t < 4; t++) kb[t] = kp[t * strideF4];
#pragma unroll
        for (int t = 0; t < 4; t++) vb[t] = vp[t * strideF4];
        kp += 4 * strideF4; vp += 4 * strideF4;

        // sc[v], v = q*4 + t
        float sc[16];
#pragma unroll
        for (int t = 0; t < 4; t++)
#pragma unroll
            for (int q = 0; q < KVG; q++)
                sc[q * 4 + t] = qv[q].x * kb[t].x + qv[q].y * kb[t].y +
                                qv[q].z * kb[t].z + qv[q].w * kb[t].w;

        // Multi-value butterfly: 16 sums in 16 SHFL.
        // After offsets 1,2,4,8 (value-halving) + 16, lane L holds total of
        // v = ((L&1)<<3)|((L&2)<<1)|((L&4)>>1)|((L&8)>>3).
#pragma unroll
        for (int j = 0; j < 8; j++) {
            float tosend = (lane & 1) ? sc[j] : sc[j + 8];
            float got = shflx(tosend, 1);
            sc[j] = ((lane & 1) ? sc[j + 8] : sc[j]) + got;
        }
#pragma unroll
        for (int j = 0; j < 4; j++) {
            float tosend = (lane & 2) ? sc[j] : sc[j + 4];
            float got = shflx(tosend, 2);
            sc[j] = ((lane & 2) ? sc[j + 4] : sc[j]) + got;
        }
#pragma unroll
        for (int j = 0; j < 2; j++) {
            float tosend = (lane & 4) ? sc[j] : sc[j + 2];
            float got = shflx(tosend, 4);
            sc[j] = ((lane & 4) ? sc[j + 2] : sc[j]) + got;
        }
        {
            float tosend = (lane & 8) ? sc[0] : sc[1];
            float got = shflx(tosend, 8);
            sc[0] = ((lane & 8) ? sc[1] : sc[0]) + got;
        }
        float s = sc[0] + shflx(sc[0], 16);

        // mask invalid tokens (per-lane predicate)
        if (t_lane >= rem) s = NEG_BIG;

        // distributed per-(q) max over t: lanes differing in bits {2,3} share q
        float mb = fmaxf(s, shflx(s, 4));
        mb = fmaxf(mb, shflx(mb, 8));

        // distributed p: one ex2 warp-wide
        float mn_lane = fmaxf(mq_lane, mb);
        float pl = ex2f(s - mn_lane);
        mq_lane = mn_lane;

        // broadcast p(q,t): src lane = (q>>1)|((q&1)<<1)|((t>>1)<<2)|((t&1)<<3)
        float pb[16];
        pb[0]  = shfli(pl, 0);  pb[1]  = shfli(pl, 8);
        pb[2]  = shfli(pl, 4);  pb[3]  = shfli(pl, 12);
        pb[4]  = shfli(pl, 2);  pb[5]  = shfli(pl, 10);
        pb[6]  = shfli(pl, 6);  pb[7]  = shfli(pl, 14);
        pb[8]  = shfli(pl, 1);  pb[9]  = shfli(pl, 9);
        pb[10] = shfli(pl, 5);  pb[11] = shfli(pl, 13);
        pb[12] = shfli(pl, 3);  pb[13] = shfli(pl, 11);
        pb[14] = shfli(pl, 7);  pb[15] = shfli(pl, 15);

        // broadcast per-q batch max: src lanes 0,2,1,3
        float mbq[4];
        mbq[0] = shfli(mb, 0); mbq[1] = shfli(mb, 2);
        mbq[2] = shfli(mb, 1); mbq[3] = shfli(mb, 3);

#pragma unroll
        for (int q = 0; q < KVG; q++) {
            float mn = fmaxf(m[q], mbq[q]);
            float alpha = ex2f(m[q] - mn);
            m[q] = mn;
            float p0 = pb[q * 4 + 0], p1 = pb[q * 4 + 1];
            float p2 = pb[q * 4 + 2], p3 = pb[q * 4 + 3];
            l[q] = l[q] * alpha + ((p0 + p1) + (p2 + p3));
            float ax = acc[q].x * alpha, ay = acc[q].y * alpha,
                  az = acc[q].z * alpha, aw = acc[q].w * alpha;
            ax += p0 * vb[0].x; ay += p0 * vb[0].y; az += p0 * vb[0].z; aw += p0 * vb[0].w;
            ax += p1 * vb[1].x; ay += p1 * vb[1].y; az += p1 * vb[1].z; aw += p1 * vb[1].w;
            ax += p2 * vb[2].x; ay += p2 * vb[2].y; az += p2 * vb[2].z; aw += p2 * vb[2].w;
            ax += p3 * vb[3].x; ay += p3 * vb[3].y; az += p3 * vb[3].z; aw += p3 * vb[3].w;
            acc[q] = make_float4(ax, ay, az, aw);
        }
    }

    // always write (empty split => m=NEG_BIG, l=0, acc=0 => zero weight in combine)
    const size_t sg = ((size_t)(b * GG + g)) * NSPLIT + split;
#pragma unroll
    for (int q = 0; q < KVG; q++) {
        float4* ap = (float4*)(g_acc + (sg * KVG + q) * DD) + lane;
        *ap = acc[q];
        if (lane == 0) g_ml[sg * KVG + q] = make_float2(m[q], l[q]);
    }
}

__global__ void __launch_bounds__(128)
attn_combine(float* __restrict__ out)
{
    const int h = blockIdx.x;
    const int b = blockIdx.y;
    const int g = h / KVG;
    const int q = h % KVG;
    const int d = threadIdx.x;

    const size_t base = ((size_t)(b * GG + g)) * NSPLIT * KVG + q;

    __shared__ float2 s_ml[NSPLIT];
    if (threadIdx.x < NSPLIT)
        s_ml[threadIdx.x] = g_ml[base + (size_t)threadIdx.x * KVG];
    __syncthreads();

    float M = NEG_BIG;
#pragma unroll
    for (int i = 0; i < NSPLIT; i++) M = fmaxf(M, s_ml[i].x);

    float num = 0.f, den = 0.f;
#pragma unroll 8
    for (int i = 0; i < NSPLIT; i++) {
        float2 ml = s_ml[i];
        float w = ex2f(ml.x - M);      // 0 for empty splits
        den += w * ml.y;
        num += w * g_acc[(base + (size_t)i * KVG) * DD + d];
    }

    out[((size_t)b * HH + h) * DD + d] = num / den;
}

extern "C" void kernel_launch(void* const* d_in, const int* in_sizes, int n_in,
                              void* d_out, int out_size)
{
    const float* Q  = (const float*)d_in[0];
    const float* K  = (const float*)d_in[1];
    const float* V  = (const float*)d_in[2];
    const int* csl  = (const int*)d_in[3];
    float* out      = (float*)d_out;

    // Launch period of 4 so ncu's "-s 5 -c 1" profiles attn_partial (index 5).
    noop_pad<<<1, 32>>>();

    dim3 grid1(NSPLIT / WPB, GG, BB);   // 8 x 8 x 16 = 1024 blocks
    attn_partial<<<grid1, 256>>>(Q, K, V, csl);

    dim3 grid2(HH, BB);                 // 32 x 16 = 512 blocks
    attn_combine<<<grid2, 128>>>(out);

    noop_pad<<<1, 32>>>();
}